// round 6
// baseline (speedup 1.0000x reference)
#include <cuda_runtime.h>
#include <cuda_bf16.h>

// Problem constants (from reference): N=32768 points, K=1024 centers, D=512.
#define N_PTS 32768
#define K_CL  1024
#define D_DIM 512

// Scratch: squared norms + deterministic per-(row, col-tile) partial sums of inv.
__device__ float g_x2[N_PTS];
__device__ float g_c2[K_CL];
__device__ float g_partial[N_PTS * 8];   // 8 column tiles of 128 over K=1024

// ---------------------------------------------------------------------------
// Kernel 1: squared norms. One block of 128 threads per row (features first,
// then centers). 512 floats = 128 float4 per row -> one float4 per thread.
// ---------------------------------------------------------------------------
__global__ void sq_kernel(const float* __restrict__ F, const float* __restrict__ C) {
    int b = blockIdx.x;
    const float* src;
    float* dst;
    if (b < N_PTS) {
        src = F + (size_t)b * D_DIM;
        dst = g_x2 + b;
    } else {
        src = C + (size_t)(b - N_PTS) * D_DIM;
        dst = g_c2 + (b - N_PTS);
    }
    float4 v = reinterpret_cast<const float4*>(src)[threadIdx.x];
    float s = v.x * v.x + v.y * v.y + v.z * v.z + v.w * v.w;
    #pragma unroll
    for (int off = 16; off > 0; off >>= 1)
        s += __shfl_down_sync(0xffffffffu, s, off);
    __shared__ float ws[4];
    if ((threadIdx.x & 31) == 0) ws[threadIdx.x >> 5] = s;
    __syncthreads();
    if (threadIdx.x == 0) *dst = ws[0] + ws[1] + ws[2] + ws[3];
}

// ---------------------------------------------------------------------------
// Kernel 2: fused SGEMM + inv + partial row sums.
//   C = A @ B^T  (A = features [N,D], B = centers [K,D], both K-major -> NT GEMM)
//   epilogue: d = x2[r] + c2[c] - 2*dot ; inv = 1/d ; out = inv ;
//             partial[r, coltile] = sum over the 128 cols of this tile.
// Tiling: BM=BN=128, BK=16, 256 threads, 8x8 per-thread tile, double-buffered.
// ---------------------------------------------------------------------------
#define BM 128
#define BN 128
#define BK 16
#define TM 8
#define TN 8
#define PAD 4   // smem row padding (stride 132, multiple of 4 for float4)

__global__ __launch_bounds__(256, 2)
void gemm_kernel(const float* __restrict__ A, const float* __restrict__ B,
                 float* __restrict__ out) {
    __shared__ __align__(16) float As[2][BK][BM + PAD];
    __shared__ __align__(16) float Bs[2][BK][BN + PAD];

    const int tid  = threadIdx.x;
    const int row0 = blockIdx.y * BM;
    const int col0 = blockIdx.x * BN;

    const int tx = tid & 15;    // 0..15 -> column group
    const int ty = tid >> 4;    // 0..15 -> row group

    // global-load mapping: 512 float4 per tile face, 256 threads -> 2 each
    const int lr0 = tid >> 2;          // rows 0..63 (and +64)
    const int lc  = (tid & 3) * 4;     // col offset 0,4,8,12 within BK

    const float* Aptr = A + (size_t)row0 * D_DIM;
    const float* Bptr = B + (size_t)col0 * D_DIM;

    float acc[TM][TN];
    #pragma unroll
    for (int i = 0; i < TM; i++)
        #pragma unroll
        for (int j = 0; j < TN; j++) acc[i][j] = 0.0f;

    float4 pa0, pa1, pb0, pb1;

    // prologue: load k-tile 0 into buffer 0
    pa0 = *reinterpret_cast<const float4*>(Aptr + (size_t)lr0        * D_DIM + lc);
    pa1 = *reinterpret_cast<const float4*>(Aptr + (size_t)(lr0 + 64) * D_DIM + lc);
    pb0 = *reinterpret_cast<const float4*>(Bptr + (size_t)lr0        * D_DIM + lc);
    pb1 = *reinterpret_cast<const float4*>(Bptr + (size_t)(lr0 + 64) * D_DIM + lc);
    As[0][lc + 0][lr0] = pa0.x; As[0][lc + 1][lr0] = pa0.y;
    As[0][lc + 2][lr0] = pa0.z; As[0][lc + 3][lr0] = pa0.w;
    As[0][lc + 0][lr0 + 64] = pa1.x; As[0][lc + 1][lr0 + 64] = pa1.y;
    As[0][lc + 2][lr0 + 64] = pa1.z; As[0][lc + 3][lr0 + 64] = pa1.w;
    Bs[0][lc + 0][lr0] = pb0.x; Bs[0][lc + 1][lr0] = pb0.y;
    Bs[0][lc + 2][lr0] = pb0.z; Bs[0][lc + 3][lr0] = pb0.w;
    Bs[0][lc + 0][lr0 + 64] = pb1.x; Bs[0][lc + 1][lr0 + 64] = pb1.y;
    Bs[0][lc + 2][lr0 + 64] = pb1.z; Bs[0][lc + 3][lr0 + 64] = pb1.w;
    __syncthreads();

    const int NT = D_DIM / BK;   // 32
    int buf = 0;

    for (int kb = 0; kb < NT; ++kb) {
        const bool has_next = (kb + 1) < NT;
        if (has_next) {
            const int ko = (kb + 1) * BK + lc;
            pa0 = *reinterpret_cast<const float4*>(Aptr + (size_t)lr0        * D_DIM + ko);
            pa1 = *reinterpret_cast<const float4*>(Aptr + (size_t)(lr0 + 64) * D_DIM + ko);
            pb0 = *reinterpret_cast<const float4*>(Bptr + (size_t)lr0        * D_DIM + ko);
            pb1 = *reinterpret_cast<const float4*>(Bptr + (size_t)(lr0 + 64) * D_DIM + ko);
        }

        #pragma unroll
        for (int kk = 0; kk < BK; ++kk) {
            float af[TM], bf[TN];
            float4 t;
            t = *reinterpret_cast<const float4*>(&As[buf][kk][ty * TM]);
            af[0] = t.x; af[1] = t.y; af[2] = t.z; af[3] = t.w;
            t = *reinterpret_cast<const float4*>(&As[buf][kk][ty * TM + 4]);
            af[4] = t.x; af[5] = t.y; af[6] = t.z; af[7] = t.w;
            t = *reinterpret_cast<const float4*>(&Bs[buf][kk][tx * TN]);
            bf[0] = t.x; bf[1] = t.y; bf[2] = t.z; bf[3] = t.w;
            t = *reinterpret_cast<const float4*>(&Bs[buf][kk][tx * TN + 4]);
            bf[4] = t.x; bf[5] = t.y; bf[6] = t.z; bf[7] = t.w;
            #pragma unroll
            for (int i = 0; i < TM; i++)
                #pragma unroll
                for (int j = 0; j < TN; j++)
                    acc[i][j] = fmaf(af[i], bf[j], acc[i][j]);
        }

        if (has_next) {
            const int nb = buf ^ 1;
            As[nb][lc + 0][lr0] = pa0.x; As[nb][lc + 1][lr0] = pa0.y;
            As[nb][lc + 2][lr0] = pa0.z; As[nb][lc + 3][lr0] = pa0.w;
            As[nb][lc + 0][lr0 + 64] = pa1.x; As[nb][lc + 1][lr0 + 64] = pa1.y;
            As[nb][lc + 2][lr0 + 64] = pa1.z; As[nb][lc + 3][lr0 + 64] = pa1.w;
            Bs[nb][lc + 0][lr0] = pb0.x; Bs[nb][lc + 1][lr0] = pb0.y;
            Bs[nb][lc + 2][lr0] = pb0.z; Bs[nb][lc + 3][lr0] = pb0.w;
            Bs[nb][lc + 0][lr0 + 64] = pb1.x; Bs[nb][lc + 1][lr0 + 64] = pb1.y;
            Bs[nb][lc + 2][lr0 + 64] = pb1.z; Bs[nb][lc + 3][lr0 + 64] = pb1.w;
            __syncthreads();
            buf ^= 1;
        }
    }

    // ---- epilogue: inv = 1/(x2 + c2 - 2*dot), store, reduce row partials ----
    float x2v[TM], c2v[TN];
    #pragma unroll
    for (int i = 0; i < TM; i++) x2v[i] = g_x2[row0 + ty * TM + i];
    #pragma unroll
    for (int j = 0; j < TN; j++) c2v[j] = g_c2[col0 + tx * TN + j];

    float rsum[TM];
    #pragma unroll
    for (int i = 0; i < TM; i++) {
        const int row = row0 + ty * TM + i;
        float inv[TN];
        float s = 0.0f;
        #pragma unroll
        for (int j = 0; j < TN; j++) {
            float d = x2v[i] + c2v[j] - 2.0f * acc[i][j];
            inv[j] = 1.0f / d;
            s += inv[j];
        }
        rsum[i] = s;
        float4* op = reinterpret_cast<float4*>(out + (size_t)row * K_CL + col0 + tx * TN);
        op[0] = make_float4(inv[0], inv[1], inv[2], inv[3]);
        op[1] = make_float4(inv[4], inv[5], inv[6], inv[7]);
    }

    // reduce over the 16 tx lanes (half-warp) -> full 128-col tile sum per row
    #pragma unroll
    for (int i = 0; i < TM; i++) {
        float v = rsum[i];
        #pragma unroll
        for (int off = 8; off > 0; off >>= 1)
            v += __shfl_down_sync(0xffffffffu, v, off, 16);
        if (tx == 0)
            g_partial[(size_t)(row0 + ty * TM + i) * 8 + blockIdx.x] = v;
    }
}

// ---------------------------------------------------------------------------
// Kernel 3: normalize. One block per row; 256 threads x 1 float4 = 1024 cols.
// Partial sum over the 8 column-tile partials done by lanes 0..7 + shuffle.
// ---------------------------------------------------------------------------
__global__ void norm_kernel(float* __restrict__ out) {
    const int row = blockIdx.x;
    __shared__ float inv_rs;
    if (threadIdx.x < 32) {
        float s = (threadIdx.x < 8) ? g_partial[(size_t)row * 8 + threadIdx.x] : 0.0f;
        #pragma unroll
        for (int off = 4; off > 0; off >>= 1)
            s += __shfl_down_sync(0xffffffffu, s, off, 8);
        if (threadIdx.x == 0) inv_rs = __frcp_rn(s);
    }
    __syncthreads();
    float4* p = reinterpret_cast<float4*>(out) + (size_t)row * (K_CL / 4) + threadIdx.x;
    float4 v = *p;
    const float r = inv_rs;
    v.x *= r; v.y *= r; v.z *= r; v.w *= r;
    *p = v;
}

// ---------------------------------------------------------------------------
extern "C" void kernel_launch(void* const* d_in, const int* in_sizes, int n_in,
                              void* d_out, int out_size) {
    const float* F = (const float*)d_in[0];   // features [32768, 512]
    const float* C = (const float*)d_in[1];   // centers  [1024, 512]
    float* out = (float*)d_out;               // mu [32768, 1024]

    sq_kernel<<<N_PTS + K_CL, 128>>>(F, C);

    dim3 grid(K_CL / BN, N_PTS / BM);         // (8, 256)
    gemm_kernel<<<grid, 256>>>(F, C, out);

    norm_kernel<<<N_PTS, 256>>>(out);
}

// round 12
// speedup vs baseline: 2.4541x; 2.4541x over previous
#include <cuda_runtime.h>
#include <cstdint>

// Problem constants: N=32768 points, K=1024 centers, D=512.
#define N_PTS 32768
#define K_CL  1024
#define D_DIM 512

__device__ float g_x2[N_PTS];
__device__ float g_c2[K_CL];
__device__ float g_partial[N_PTS * 8];   // 8 column tiles of 128 over K=1024

// ---------------------------------------------------------------------------
// Kernel 1: squared norms (identical to the passing baseline).
// ---------------------------------------------------------------------------
__global__ void sq_kernel(const float* __restrict__ F, const float* __restrict__ C) {
    int b = blockIdx.x;
    const float* src;
    float* dst;
    if (b < N_PTS) {
        src = F + (size_t)b * D_DIM;
        dst = g_x2 + b;
    } else {
        src = C + (size_t)(b - N_PTS) * D_DIM;
        dst = g_c2 + (b - N_PTS);
    }
    float4 v = reinterpret_cast<const float4*>(src)[threadIdx.x];
    float s = v.x * v.x + v.y * v.y + v.z * v.z + v.w * v.w;
    #pragma unroll
    for (int off = 16; off > 0; off >>= 1)
        s += __shfl_down_sync(0xffffffffu, s, off);
    __shared__ float ws[4];
    if ((threadIdx.x & 31) == 0) ws[threadIdx.x >> 5] = s;
    __syncthreads();
    if (threadIdx.x == 0) *dst = ws[0] + ws[1] + ws[2] + ws[3];
}

// ---------------------------------------------------------------------------
// Kernel 2: tf32 mma.sync GEMM + fused 1/d epilogue + deterministic partials.
//   BM=BN=128, BK=32, 256 threads (8 warps, 2x4 grid, 64x32 warp tiles).
//   smem: A/B faces in [row][k] layout, pad 4 -> fragment LDS is conflict-free.
// ---------------------------------------------------------------------------
#define BM 128
#define BN 128
#define BK 32
#define NIT (D_DIM / BK)     // 16
#define SROW (BK + 4)        // 36 floats per smem row
#define FACE (BM * SROW)     // 4608 floats per face
// float offsets inside dynamic smem
#define A_OFF(b) ((b) * FACE)
#define B_OFF(b) (2 * FACE + (b) * FACE)
#define RS_OFF   (4 * FACE)              // rowsum[4][128]
#define SMEM_FLOATS (4 * FACE + 512)
#define SMEM_BYTES  (SMEM_FLOATS * 4)    // 75776 B

#define CP_ASYNC16(sm, g) \
    asm volatile("cp.async.cg.shared.global [%0], [%1], 16;" \
                 :: "r"((uint32_t)(sm)), "l"(g) : "memory")
#define CP_COMMIT() asm volatile("cp.async.commit_group;" ::: "memory")
#define CP_WAIT1()  asm volatile("cp.async.wait_group 1;" ::: "memory")
#define CP_WAIT0()  asm volatile("cp.async.wait_group 0;" ::: "memory")

__device__ __forceinline__ uint32_t smem_u32(const void* p) {
    uint32_t a;
    asm("{ .reg .u64 t; cvta.to.shared.u64 t, %1; cvt.u32.u64 %0, t; }"
        : "=r"(a) : "l"(p));
    return a;
}
__device__ __forceinline__ uint32_t f2tf32(float v) {
    uint32_t r;
    asm("cvt.rna.tf32.f32 %0, %1;" : "=r"(r) : "f"(v));
    return r;
}
__device__ __forceinline__ void mma_tf32(float* c, uint32_t a0, uint32_t a1,
                                         uint32_t a2, uint32_t a3,
                                         uint32_t b0, uint32_t b1) {
    asm volatile(
        "mma.sync.aligned.m16n8k8.row.col.f32.tf32.tf32.f32 "
        "{%0,%1,%2,%3}, {%4,%5,%6,%7}, {%8,%9}, {%0,%1,%2,%3};"
        : "+f"(c[0]), "+f"(c[1]), "+f"(c[2]), "+f"(c[3])
        : "r"(a0), "r"(a1), "r"(a2), "r"(a3), "r"(b0), "r"(b1));
}

// load one BK-chunk of A and B into buffer `buf` via cp.async (one commit)
__device__ __forceinline__ void load_tiles(uint32_t sb, float* smemf, int buf,
        int kb, const float* Ag, const float* Bg, int tid) {
    // A: 128 rows x 8 16B chunks = 1024 -> 4 per thread; same for B
    #pragma unroll
    for (int u = 0; u < 4; u++) {
        const int idx = tid + u * 256;
        const int r = idx >> 3, ch = idx & 7;
        const uint32_t sa = sb + (uint32_t)(A_OFF(buf) + r * SROW + ch * 4) * 4u;
        CP_ASYNC16(sa, Ag + (size_t)r * D_DIM + kb + ch * 4);
    }
    #pragma unroll
    for (int u = 0; u < 4; u++) {
        const int idx = tid + u * 256;
        const int r = idx >> 3, ch = idx & 7;
        const uint32_t sa = sb + (uint32_t)(B_OFF(buf) + r * SROW + ch * 4) * 4u;
        CP_ASYNC16(sa, Bg + (size_t)r * D_DIM + kb + ch * 4);
    }
    CP_COMMIT();
}

__global__ __launch_bounds__(256, 2)
void tf32_gemm_kernel(const float* __restrict__ A, const float* __restrict__ B,
                      float* __restrict__ out) {
    extern __shared__ float smemf[];
    const uint32_t sb = smem_u32(smemf);
    const int tid  = threadIdx.x;
    const int wid  = tid >> 5, lane = tid & 31;
    const int wm   = wid & 1;          // 0..1 -> 64-row slab
    const int wn   = wid >> 1;         // 0..3 -> 32-col slab
    const int q    = lane >> 2;        // groupID (row within fragment)
    const int tcol = lane & 3;         // threadID_in_group
    const int row0 = blockIdx.y * BM;
    const int col0 = blockIdx.x * BN;

    const float* Ag = A + (size_t)row0 * D_DIM;
    const float* Bg = B + (size_t)col0 * D_DIM;

    float acc[4][4][4];
    #pragma unroll
    for (int i = 0; i < 4; i++)
        #pragma unroll
        for (int j = 0; j < 4; j++)
            #pragma unroll
            for (int r = 0; r < 4; r++) acc[i][j][r] = 0.0f;

    load_tiles(sb, smemf, 0, 0, Ag, Bg, tid);

    for (int it = 0; it < NIT; it++) {
        if (it + 1 < NIT) load_tiles(sb, smemf, (it + 1) & 1, (it + 1) * BK, Ag, Bg, tid);
        if (it + 1 < NIT) CP_WAIT1(); else CP_WAIT0();
        __syncthreads();

        const int buf = it & 1;
        const float* Asb = smemf + A_OFF(buf);
        const float* Bsb = smemf + B_OFF(buf);

        #pragma unroll
        for (int ks = 0; ks < 4; ks++) {
            const int k0 = ks * 8;
            uint32_t af[4][4];
            #pragma unroll
            for (int mt = 0; mt < 4; mt++) {
                const int rb = wm * 64 + mt * 16;
                af[mt][0] = f2tf32(Asb[(rb + q)     * SROW + k0 + tcol]);
                af[mt][1] = f2tf32(Asb[(rb + q + 8) * SROW + k0 + tcol]);
                af[mt][2] = f2tf32(Asb[(rb + q)     * SROW + k0 + tcol + 4]);
                af[mt][3] = f2tf32(Asb[(rb + q + 8) * SROW + k0 + tcol + 4]);
            }
            uint32_t bf[4][2];
            #pragma unroll
            for (int nt = 0; nt < 4; nt++) {
                const int cb = wn * 32 + nt * 8;
                bf[nt][0] = f2tf32(Bsb[(cb + q) * SROW + k0 + tcol]);
                bf[nt][1] = f2tf32(Bsb[(cb + q) * SROW + k0 + tcol + 4]);
            }
            #pragma unroll
            for (int mt = 0; mt < 4; mt++)
                #pragma unroll
                for (int nt = 0; nt < 4; nt++)
                    mma_tf32(acc[mt][nt], af[mt][0], af[mt][1], af[mt][2], af[mt][3],
                             bf[nt][0], bf[nt][1]);
        }
        __syncthreads();
    }

    // ---- fused epilogue: inv = 1/(x2 + c2 - 2*dot) ----
    float x2a[4], x2b[4];
    #pragma unroll
    for (int mt = 0; mt < 4; mt++) {
        x2a[mt] = g_x2[row0 + wm * 64 + mt * 16 + q];
        x2b[mt] = g_x2[row0 + wm * 64 + mt * 16 + q + 8];
    }
    float c2v0[4], c2v1[4];
    #pragma unroll
    for (int nt = 0; nt < 4; nt++) {
        const int gc = col0 + wn * 32 + nt * 8 + 2 * tcol;
        c2v0[nt] = g_c2[gc];
        c2v1[nt] = g_c2[gc + 1];
    }

    float rsA[4] = {0.f, 0.f, 0.f, 0.f};
    float rsB[4] = {0.f, 0.f, 0.f, 0.f};
    #pragma unroll
    for (int mt = 0; mt < 4; mt++) {
        const int r = row0 + wm * 64 + mt * 16 + q;
        #pragma unroll
        for (int nt = 0; nt < 4; nt++) {
            const int gc = col0 + wn * 32 + nt * 8 + 2 * tcol;
            const float i0 = 1.0f / (x2a[mt] + c2v0[nt] - 2.0f * acc[mt][nt][0]);
            const float i1 = 1.0f / (x2a[mt] + c2v1[nt] - 2.0f * acc[mt][nt][1]);
            const float i2 = 1.0f / (x2b[mt] + c2v0[nt] - 2.0f * acc[mt][nt][2]);
            const float i3 = 1.0f / (x2b[mt] + c2v1[nt] - 2.0f * acc[mt][nt][3]);
            *reinterpret_cast<float2*>(out + (size_t)r * K_CL + gc)       = make_float2(i0, i1);
            *reinterpret_cast<float2*>(out + (size_t)(r + 8) * K_CL + gc) = make_float2(i2, i3);
            rsA[mt] += i0 + i1;
            rsB[mt] += i2 + i3;
        }
    }

    // quad reduction (lanes sharing a row are lane^1, lane^2)
    #pragma unroll
    for (int mt = 0; mt < 4; mt++) {
        rsA[mt] += __shfl_xor_sync(0xffffffffu, rsA[mt], 1);
        rsA[mt] += __shfl_xor_sync(0xffffffffu, rsA[mt], 2);
        rsB[mt] += __shfl_xor_sync(0xffffffffu, rsB[mt], 1);
        rsB[mt] += __shfl_xor_sync(0xffffffffu, rsB[mt], 2);
    }
    float* rowsum = smemf + RS_OFF;   // [4 warps_n][128 rows]
    if (tcol == 0) {
        #pragma unroll
        for (int mt = 0; mt < 4; mt++) {
            rowsum[wn * 128 + wm * 64 + mt * 16 + q]     = rsA[mt];
            rowsum[wn * 128 + wm * 64 + mt * 16 + q + 8] = rsB[mt];
        }
    }
    __syncthreads();
    if (tid < 128) {
        const float s = rowsum[tid] + rowsum[128 + tid] + rowsum[256 + tid] + rowsum[384 + tid];
        g_partial[(size_t)(row0 + tid) * 8 + blockIdx.x] = s;
    }
}

// ---------------------------------------------------------------------------
// Kernel 3: normalize (identical to the passing baseline).
// ---------------------------------------------------------------------------
__global__ void norm_kernel(float* __restrict__ out) {
    const int row = blockIdx.x;
    __shared__ float inv_rs;
    if (threadIdx.x < 32) {
        float s = (threadIdx.x < 8) ? g_partial[(size_t)row * 8 + threadIdx.x] : 0.0f;
        #pragma unroll
        for (int off = 4; off > 0; off >>= 1)
            s += __shfl_down_sync(0xffffffffu, s, off, 8);
        if (threadIdx.x == 0) inv_rs = __frcp_rn(s);
    }
    __syncthreads();
    float4* p = reinterpret_cast<float4*>(out) + (size_t)row * (K_CL / 4) + threadIdx.x;
    float4 v = *p;
    const float r = inv_rs;
    v.x *= r; v.y *= r; v.z *= r; v.w *= r;
    *p = v;
}

// ---------------------------------------------------------------------------
extern "C" void kernel_launch(void* const* d_in, const int* in_sizes, int n_in,
                              void* d_out, int out_size) {
    const float* F = (const float*)d_in[0];   // features [32768, 512]
    const float* C = (const float*)d_in[1];   // centers  [1024, 512]
    float* out = (float*)d_out;               // mu [32768, 1024]

    sq_kernel<<<N_PTS + K_CL, 128>>>(F, C);

    cudaFuncSetAttribute(tf32_gemm_kernel,
                         cudaFuncAttributeMaxDynamicSharedMemorySize, SMEM_BYTES);
    dim3 grid(K_CL / BN, N_PTS / BM);         // (8, 256)
    tf32_gemm_kernel<<<grid, 256, SMEM_BYTES>>>(F, C, out);

    norm_kernel<<<N_PTS, 256>>>(out);
}